// round 4
// baseline (speedup 1.0000x reference)
#include <cuda_runtime.h>

// FastfoodTransform: out[b, j] = S[j] * FWHT1024_perstack( G[j'] * FWHT1024_perstack(B∘x)[P[j']] ) + bias[j]
// BATCH=16384, IN=1024 (=IN_EXT), NSTACK=4, OUT=4096.
//
// One row per 128-thread block; warp w owns stack w (1024 elems, 32 per lane).
// FWHT stages commute (tensor product over index bits), so:
//   layout A: lane l holds elems [32l, 32l+32)  -> bits 0..4 in registers (5 stages, pure FADD)
//   stride-33 shared transpose (bank-conflict-free both ways)
//   layout B: lane l holds elems {l + 32k}      -> bits 5..9 in registers (5 stages)
// The permutation across all 4096 elems goes through a block-wide shared buffer
// that aliases the transpose scratch (barriers order the reuse).

static __device__ __forceinline__ void fwht32(float v[32]) {
#pragma unroll
    for (int h = 1; h < 32; h <<= 1) {
#pragma unroll
        for (int base = 0; base < 32; base += 2 * h) {
#pragma unroll
            for (int r = 0; r < h; r++) {
                float a = v[base + r];
                float b = v[base + r + h];
                v[base + r]     = a + b;
                v[base + r + h] = a - b;
            }
        }
    }
}

extern "C" __global__ void __launch_bounds__(128)
fastfood_kernel(const float* __restrict__ x,
                const float* __restrict__ B,
                const float* __restrict__ G,
                const float* __restrict__ S,
                const float* __restrict__ bias,
                const int*   __restrict__ P,
                float* __restrict__ out)
{
    // 4 warps x 1056 floats (33-stride padded 32x32 transpose tiles).
    // The first 4096 floats double as the block-wide permute buffer.
    __shared__ float buf[4224];

    const int row = blockIdx.x;
    const int l   = threadIdx.x & 31;   // lane
    const int w   = threadIdx.x >> 5;   // warp == stack index

    float v[32];

    // ---- load x chunk and multiply by B: element i = 32*l + r of stack w ----
    {
        const float4* x4 = reinterpret_cast<const float4*>(x + (size_t)row * 1024 + 32 * l);
        const float4* B4 = reinterpret_cast<const float4*>(B + w * 1024 + 32 * l);
#pragma unroll
        for (int q = 0; q < 8; q++) {
            float4 xv = x4[q];
            float4 bv = B4[q];
            v[4 * q + 0] = xv.x * bv.x;
            v[4 * q + 1] = xv.y * bv.y;
            v[4 * q + 2] = xv.z * bv.z;
            v[4 * q + 3] = xv.w * bv.w;
        }
    }

    // ---- FWHT #1, bits 0..4 (h = 1..16) in registers ----
    fwht32(v);

    // ---- transpose within warp via padded shared (conflict-free) ----
    float* tb = buf + w * 1056;
#pragma unroll
    for (int r = 0; r < 32; r++) tb[33 * l + r] = v[r];   // banks (l+r)%32: distinct
    __syncwarp();
#pragma unroll
    for (int k = 0; k < 32; k++) v[k] = tb[33 * k + l];   // banks (k+l)%32: distinct
    // now lane l holds elems {l + 32k}; register index k = bits 5..9

    // ---- FWHT #1, bits 5..9 (h = 32..512) in registers ----
    fwht32(v);

    // ---- stage full 4096-elem FWHT1 result into shared for the permutation ----
    // buf[0..4096) aliases other warps' transpose tiles -> barrier before overwrite
    __syncthreads();
#pragma unroll
    for (int k = 0; k < 32; k++) buf[w * 1024 + 32 * k + l] = v[k];  // bank = l: conflict-free
    __syncthreads();

    // ---- permuted gather + G multiply, directly into layout B of FWHT #2 ----
    // warp w, lane l produces j_local = l + 32k  (global j = w*1024 + l + 32k)
    {
        const int base = w * 1024 + l;
        int pk[32];
#pragma unroll
        for (int k = 0; k < 32; k++) pk[k] = P[base + 32 * k];   // coalesced LDG.32
#pragma unroll
        for (int k = 0; k < 32; k++) v[k] = buf[pk[k]];          // random LDS gather
#pragma unroll
        for (int k = 0; k < 32; k++) v[k] *= G[base + 32 * k];   // coalesced LDG.32
    }

    // ---- FWHT #2, bits 5..9 (register index k) ----
    fwht32(v);

    // ---- transpose back to contiguous layout (barrier: buf still being gathered) ----
    __syncthreads();
#pragma unroll
    for (int k = 0; k < 32; k++) tb[33 * k + l] = v[k];
    __syncwarp();
#pragma unroll
    for (int r = 0; r < 32; r++) v[r] = tb[33 * l + r];
    // now lane l holds elems j_local in [32l, 32l+32)

    // ---- FWHT #2, bits 0..4 ----
    fwht32(v);

    // ---- epilogue: S * v + bias, vectorized store ----
    {
        const int j0 = w * 1024 + 32 * l;
        const float4* S4 = reinterpret_cast<const float4*>(S + j0);
        const float4* b4 = reinterpret_cast<const float4*>(bias + j0);
        float4* o4 = reinterpret_cast<float4*>(out + (size_t)row * 4096 + j0);
#pragma unroll
        for (int q = 0; q < 8; q++) {
            float4 sv = S4[q];
            float4 bb = b4[q];
            float4 ov;
            ov.x = fmaf(sv.x, v[4 * q + 0], bb.x);
            ov.y = fmaf(sv.y, v[4 * q + 1], bb.y);
            ov.z = fmaf(sv.z, v[4 * q + 2], bb.z);
            ov.w = fmaf(sv.w, v[4 * q + 3], bb.w);
            o4[q] = ov;
        }
    }
}

extern "C" void kernel_launch(void* const* d_in, const int* in_sizes, int n_in,
                              void* d_out, int out_size)
{
    const float* x    = (const float*)d_in[0];   // (16384, 1024) f32
    const float* B    = (const float*)d_in[1];   // (4, 1024) f32
    const float* G    = (const float*)d_in[2];   // (4, 1024) f32
    const float* S    = (const float*)d_in[3];   // (4, 1024) f32
    const float* bias = (const float*)d_in[4];   // (4096,) f32
    const int*   P    = (const int*)d_in[5];     // (4096,) i32
    float* out = (float*)d_out;

    const int batch = in_sizes[0] / 1024;        // 16384
    fastfood_kernel<<<batch, 128>>>(x, B, G, S, bias, P, out);
}

// round 5
// speedup vs baseline: 1.6318x; 1.6318x over previous
#include <cuda_runtime.h>

// FastfoodTransform: out[b,j] = S[j]*FWHT1024_stack( G∘ permute_P( FWHT1024_stack(B∘x) ) ) + bias[j]
// BATCH=16384, IN=IN_EXT=1024, NSTACK=4, OUT=4096.
//
// R5 strategy: L1tex-wavefront bound (94.8% SOL in R4). Weights (B,G,S,bias,P)
// are identical across all blocks; their reloads were ~31% of L1 wavefronts.
// -> 8 rows per block, weights register-resident for the whole block.
// Gv/pk are held in the post-permute ("layout B") order so the per-row gather
// is a single LDS + FMUL per element.
//
// Per row, per warp (stack w):
//   layout A: lane l holds elems [32l,32l+32) -> fwht32 does FWHT bits 0..4
//   stride-33 padded per-warp transpose (conflict-free, __syncwarp only)
//   layout B: lane l holds elems {l+32k}      -> fwht32 does FWHT bits 5..9
//   stage into block-wide buf, __syncthreads, random gather buf[pk]∘Gv,
//   fwht32 (bits 5..9), transpose back, fwht32 (bits 0..4), S*v+bias, store.

static __device__ __forceinline__ void fwht32(float v[32]) {
#pragma unroll
    for (int h = 1; h < 32; h <<= 1) {
#pragma unroll
        for (int base = 0; base < 32; base += 2 * h) {
#pragma unroll
            for (int r = 0; r < h; r++) {
                float a = v[base + r];
                float b = v[base + r + h];
                v[base + r]     = a + b;
                v[base + r + h] = a - b;
            }
        }
    }
}

#define ROWS_PER_BLOCK 8

extern "C" __global__ void __launch_bounds__(128, 2)
fastfood_kernel(const float* __restrict__ x,
                const float* __restrict__ B,
                const float* __restrict__ G,
                const float* __restrict__ S,
                const float* __restrict__ bias,
                const int*   __restrict__ P,
                float* __restrict__ out,
                int batch)
{
    // Separate buffers: block-wide permute buffer + per-warp transpose tiles
    // (padded stride 33 -> conflict-free both directions, warp-private so only
    // __syncwarp is needed around transposes).
    __shared__ float buf[4096];
    __shared__ float tbuf[4][1056];

    const int l = threadIdx.x & 31;       // lane
    const int w = threadIdx.x >> 5;       // warp == stack
    const int a0   = w * 1024 + 32 * l;   // layout-A base (contiguous 32 elems)
    const int bse  = w * 1024 + l;        // layout-B base (stride-32 elems)
    float* tb = tbuf[w];

    // ---- register-resident weights (loaded once per block) ----
    float Bv[32], Sv[32], Biv[32];        // layout A
    float Gv[32];                         // layout B
    int   pk[32];                         // gather indices, layout B
    {
        const float4* B4 = reinterpret_cast<const float4*>(B + a0);
        const float4* S4 = reinterpret_cast<const float4*>(S + a0);
        const float4* b4 = reinterpret_cast<const float4*>(bias + a0);
#pragma unroll
        for (int q = 0; q < 8; q++) {
            float4 t;
            t = B4[q]; Bv[4*q+0]=t.x; Bv[4*q+1]=t.y; Bv[4*q+2]=t.z; Bv[4*q+3]=t.w;
            t = S4[q]; Sv[4*q+0]=t.x; Sv[4*q+1]=t.y; Sv[4*q+2]=t.z; Sv[4*q+3]=t.w;
            t = b4[q]; Biv[4*q+0]=t.x; Biv[4*q+1]=t.y; Biv[4*q+2]=t.z; Biv[4*q+3]=t.w;
        }
#pragma unroll
        for (int k = 0; k < 32; k++) pk[k] = P[bse + 32 * k];   // coalesced
#pragma unroll
        for (int k = 0; k < 32; k++) Gv[k] = G[bse + 32 * k];   // coalesced
    }

    const int row0 = blockIdx.x * ROWS_PER_BLOCK;

    for (int i = 0; i < ROWS_PER_BLOCK; i++) {
        const int row = row0 + i;
        if (row >= batch) break;          // uniform per block

        float v[32];

        // ---- load x (layout A, float4) and multiply by B ----
        {
            const float4* x4 = reinterpret_cast<const float4*>(x + (size_t)row * 1024 + 32 * l);
#pragma unroll
            for (int q = 0; q < 8; q++) {
                float4 xv = x4[q];
                v[4*q+0] = xv.x * Bv[4*q+0];
                v[4*q+1] = xv.y * Bv[4*q+1];
                v[4*q+2] = xv.z * Bv[4*q+2];
                v[4*q+3] = xv.w * Bv[4*q+3];
            }
        }

        // ---- FWHT #1 bits 0..4 ----
        fwht32(v);

        // ---- transpose A -> B (conflict-free, warp-local) ----
        __syncwarp();                     // tb reads of previous row done
#pragma unroll
        for (int r = 0; r < 32; r++) tb[33 * l + r] = v[r];
        __syncwarp();
#pragma unroll
        for (int k = 0; k < 32; k++) v[k] = tb[33 * k + l];

        // ---- FWHT #1 bits 5..9 ----
        fwht32(v);

        // ---- stage full FWHT1 result for the permutation ----
        __syncthreads();                  // previous row's gathers finished
#pragma unroll
        for (int k = 0; k < 32; k++) buf[w * 1024 + 32 * k + l] = v[k];  // bank=l
        __syncthreads();                  // buf complete

        // ---- permuted gather ∘ G, directly in layout B ----
#pragma unroll
        for (int k = 0; k < 32; k++) v[k] = buf[pk[k]];
#pragma unroll
        for (int k = 0; k < 32; k++) v[k] *= Gv[k];

        // ---- FWHT #2 bits 5..9 ----
        fwht32(v);

        // ---- transpose B -> A ----
        __syncwarp();
#pragma unroll
        for (int k = 0; k < 32; k++) tb[33 * k + l] = v[k];
        __syncwarp();
#pragma unroll
        for (int r = 0; r < 32; r++) v[r] = tb[33 * l + r];

        // ---- FWHT #2 bits 0..4 ----
        fwht32(v);

        // ---- epilogue: S*v + bias, vectorized store ----
        {
            float4* o4 = reinterpret_cast<float4*>(out + (size_t)row * 4096 + a0);
#pragma unroll
            for (int q = 0; q < 8; q++) {
                float4 ov;
                ov.x = fmaf(Sv[4*q+0], v[4*q+0], Biv[4*q+0]);
                ov.y = fmaf(Sv[4*q+1], v[4*q+1], Biv[4*q+1]);
                ov.z = fmaf(Sv[4*q+2], v[4*q+2], Biv[4*q+2]);
                ov.w = fmaf(Sv[4*q+3], v[4*q+3], Biv[4*q+3]);
                o4[q] = ov;
            }
        }
    }
}

extern "C" void kernel_launch(void* const* d_in, const int* in_sizes, int n_in,
                              void* d_out, int out_size)
{
    const float* x    = (const float*)d_in[0];   // (16384, 1024) f32
    const float* B    = (const float*)d_in[1];   // (4, 1024) f32
    const float* G    = (const float*)d_in[2];   // (4, 1024) f32
    const float* S    = (const float*)d_in[3];   // (4, 1024) f32
    const float* bias = (const float*)d_in[4];   // (4096,) f32
    const int*   P    = (const int*)d_in[5];     // (4096,) i32
    float* out = (float*)d_out;

    const int batch = in_sizes[0] / 1024;        // 16384
    const int grid  = (batch + ROWS_PER_BLOCK - 1) / ROWS_PER_BLOCK;
    fastfood_kernel<<<grid, 128>>>(x, B, G, S, bias, P, out, batch);
}